// round 15
// baseline (speedup 1.0000x reference)
#include <cuda_runtime.h>
#include <cuda_bf16.h>
#include <math.h>
#include <cstdint>

// ---------------------------------------------------------------------------
// TropicalMLP: trop_linear(x;W,b) = log(exp(x) @ exp(W)^T) + b  (temp=1).
// exp values split fp32 = hi(bf16) + lo(bf16); GEMM = hh + hl + lh via
// mma.sync.m16n8k16 bf16.  R14: split-K x4 -> 512 CTAs, 3 CTAs/SM
// (launch_bounds(256,3)); ln_fuse reduces 4 partials.  Inner loop unchanged
// from R13 (64x64 tile, warp 16x32, 3-stage cp.async).
// ---------------------------------------------------------------------------

#define KDIM 512
#define BKC  32          // K per chunk
#define LDSP 40          // padded row stride in bf16 (80 B)

__device__ float          g_P[4 * 1024 * 512];   // split-K partials
__device__ __nv_bfloat16  g_Ah[1024 * 512];
__device__ __nv_bfloat16  g_Al[1024 * 512];
__device__ __nv_bfloat16  g_W1h[512 * 512];
__device__ __nv_bfloat16  g_W1l[512 * 512];
__device__ __nv_bfloat16  g_W2h[512 * 512];
__device__ __nv_bfloat16  g_W2l[512 * 512];
__device__ __nv_bfloat16  g_W3h[256 * 512];
__device__ __nv_bfloat16  g_W3l[256 * 512];

__device__ __forceinline__ uint32_t smem_to_u32(const void* p) {
    uint32_t a;
    asm("{ .reg .u64 t; cvta.to.shared.u64 t, %1; cvt.u32.u64 %0, t; }"
        : "=r"(a) : "l"(p));
    return a;
}

#define LDSM4(r0, r1, r2, r3, addr)                                        \
    asm volatile("ldmatrix.sync.aligned.m8n8.x4.shared.b16 {%0,%1,%2,%3}, [%4];" \
                 : "=r"(r0), "=r"(r1), "=r"(r2), "=r"(r3) : "r"(addr))

#define MMA16816(d, a, b)                                                  \
    asm volatile("mma.sync.aligned.m16n8k16.row.col.f32.bf16.bf16.f32 "    \
                 "{%0,%1,%2,%3}, {%4,%5,%6,%7}, {%8,%9}, {%0,%1,%2,%3};"   \
                 : "+f"((d)[0]), "+f"((d)[1]), "+f"((d)[2]), "+f"((d)[3])  \
                 : "r"((a)[0]), "r"((a)[1]), "r"((a)[2]), "r"((a)[3]),     \
                   "r"((b)[0]), "r"((b)[1]))

#define CP_ASYNC16(dst, src)                                               \
    asm volatile("cp.async.ca.shared.global [%0], [%1], 16;"               \
                 :: "r"(dst), "l"(src))
#define CP_COMMIT() asm volatile("cp.async.commit_group;" ::: "memory")
#define CP_WAIT1()  asm volatile("cp.async.wait_group 1;" ::: "memory")

// ---------------------------------------------------------------------------
// exp + hi/lo split of x, w1, w2, w3 (float4 granular)
// ---------------------------------------------------------------------------
__global__ __launch_bounds__(256) void exp_split_kernel(
    const float* __restrict__ x,  __nv_bfloat16* __restrict__ xh, __nv_bfloat16* __restrict__ xl,
    const float* __restrict__ w1, __nv_bfloat16* __restrict__ w1h, __nv_bfloat16* __restrict__ w1l,
    const float* __restrict__ w2, __nv_bfloat16* __restrict__ w2h, __nv_bfloat16* __restrict__ w2l,
    const float* __restrict__ w3, __nv_bfloat16* __restrict__ w3h, __nv_bfloat16* __restrict__ w3l) {
    int i = blockIdx.x * 256 + threadIdx.x;  // float4 index
    const float* s; __nv_bfloat16 *dh, *dl; int off;
    if (i < 131072)      { s = x;  dh = xh;  dl = xl;  off = i; }
    else if (i < 196608) { s = w1; dh = w1h; dl = w1l; off = i - 131072; }
    else if (i < 262144) { s = w2; dh = w2h; dl = w2l; off = i - 196608; }
    else                 { s = w3; dh = w3h; dl = w3l; off = i - 262144; }
    float4 v = reinterpret_cast<const float4*>(s)[off];
    float e[4] = {expf(v.x), expf(v.y), expf(v.z), expf(v.w)};
#pragma unroll
    for (int j = 0; j < 4; j++) {
        __nv_bfloat16 hi = __float2bfloat16(e[j]);
        __nv_bfloat16 lo = __float2bfloat16(e[j] - __bfloat162float(hi));
        dh[off * 4 + j] = hi;
        dl[off * 4 + j] = lo;
    }
}

// ---------------------------------------------------------------------------
// HMMA GEMM:  acc[m,n] = (Ah+Al)[m,kz-chunk].(Bh+Bl)[n,kz-chunk]
// BM x 64 CTA tile, 8 warps (warp tile 16 x WN), KCH chunks of 32 K each,
// 3-stage cp.async pipeline, whole-chunk fragment preload, 3 CTAs/SM.
// RAW=true : store raw partial sums at C + kz*1024*OUT (reduced in ln_fuse).
// RAW=false: full K in one CTA; epilogue log + bias.
// ---------------------------------------------------------------------------
template <int BM, int WN, int KCH, bool RAW>
__global__ __launch_bounds__(256, 3) void gemm_mma(
    const __nv_bfloat16* __restrict__ Ah, const __nv_bfloat16* __restrict__ Al,
    const __nv_bfloat16* __restrict__ Bh, const __nv_bfloat16* __restrict__ Bl,
    const float* __restrict__ bias, float* __restrict__ C, int OUT) {
    constexpr int BN = 64, S = 3;
    constexpr int PN  = WN / 16;     // B 16-row groups per warp (1 or 2)
    constexpr int TNC = WN / 8;      // mma n-tiles per warp (2 or 4)
    constexpr int NWN = BN / WN;     // warps along N
    static_assert((BM / 16) * NWN == 8, "8 warps");

    __shared__ __align__(16) __nv_bfloat16 sA[S][2][BM][LDSP];
    __shared__ __align__(16) __nv_bfloat16 sB[S][2][BN][LDSP];

    const int tid  = threadIdx.x;
    const int lane = tid & 31;
    const int warp = tid >> 5;
    const int wm = (warp / NWN) * 16;
    const int wn = (warp % NWN) * WN;
    const int bm = blockIdx.y * BM;
    const int bn = blockIdx.x * BN;
    const int kz = blockIdx.z;
    const int kbase = kz * KCH * BKC;

    const uint32_t sAb = smem_to_u32(sA);
    const uint32_t sBb = smem_to_u32(sB);
    constexpr uint32_t A_ARR = BM * LDSP * 2, A_STG = 2 * A_ARR;
    constexpr uint32_t B_ARR = BN * LDSP * 2, B_STG = 2 * B_ARR;

    // cp.async mapping: thread -> (row, 16B seg)
    const int grow = tid >> 2, gseg = tid & 3;
    const __nv_bfloat16* gpA[2] = {Ah + (size_t)bm * KDIM, Al + (size_t)bm * KDIM};
    const __nv_bfloat16* gpB[2] = {Bh + (size_t)bn * KDIM, Bl + (size_t)bn * KDIM};

    // ldmatrix lane addressing
    const int rowA = lane & 15, chA = lane >> 4;
    const int qB = lane >> 3;
    const int rowB = ((qB >> 1) << 3) + (lane & 7), colB = (qB & 1) * 8;
    uint32_t aBase[2], bBase[2][PN];
#pragma unroll
    for (int a = 0; a < 2; a++)
        aBase[a] = sAb + a * A_ARR + ((uint32_t)(wm + rowA) * LDSP + chA * 8) * 2;
#pragma unroll
    for (int a = 0; a < 2; a++)
#pragma unroll
        for (int p = 0; p < PN; p++)
            bBase[a][p] = sBb + a * B_ARR +
                ((uint32_t)(wn + p * 16 + rowB) * LDSP + colB) * 2;

    float acc[TNC][4] = {};

    auto copy_chunk = [&](int c, int buf) {
        const int k0 = kbase + c * BKC;
        if (grow < BM) {
#pragma unroll
            for (int a = 0; a < 2; a++) {
                uint32_t dst = sAb + buf * A_STG + a * A_ARR +
                               ((uint32_t)grow * LDSP + gseg * 8) * 2;
                CP_ASYNC16(dst, gpA[a] + (size_t)grow * KDIM + k0 + gseg * 8);
            }
        }
#pragma unroll
        for (int a = 0; a < 2; a++) {
            uint32_t dst = sBb + buf * B_STG + a * B_ARR +
                           ((uint32_t)grow * LDSP + gseg * 8) * 2;
            CP_ASYNC16(dst, gpB[a] + (size_t)grow * KDIM + k0 + gseg * 8);
        }
        CP_COMMIT();
    };

    copy_chunk(0, 0);
    copy_chunk(1, 1);

#pragma unroll 1
    for (int c = 0; c < KCH; c++) {
        CP_WAIT1();              // chunk c landed
        __syncthreads();
        if (c + 2 < KCH) copy_chunk(c + 2, (c + 2) % S);
        else             CP_COMMIT();   // keep group numbering uniform

        const uint32_t ao = (c % S) * A_STG, bo = (c % S) * B_STG;
        // preload ALL fragments for both 16-K steps of this chunk
        uint32_t ah[2][4], al[2][4], bh[2][PN][4], bl[2][PN][4];
#pragma unroll
        for (int s = 0; s < 2; s++) {
            const uint32_t so = s * 32;
            LDSM4(ah[s][0], ah[s][1], ah[s][2], ah[s][3], aBase[0] + ao + so);
            LDSM4(al[s][0], al[s][1], al[s][2], al[s][3], aBase[1] + ao + so);
#pragma unroll
            for (int p = 0; p < PN; p++) {
                LDSM4(bh[s][p][0], bh[s][p][1], bh[s][p][2], bh[s][p][3],
                      bBase[0][p] + bo + so);
                LDSM4(bl[s][p][0], bl[s][p][1], bl[s][p][2], bl[s][p][3],
                      bBase[1][p] + bo + so);
            }
        }
#pragma unroll
        for (int s = 0; s < 2; s++)
#pragma unroll
            for (int tn = 0; tn < TNC; tn++) {
                uint32_t* bhp = &bh[s][tn >> 1][(tn & 1) * 2];
                uint32_t* blp = &bl[s][tn >> 1][(tn & 1) * 2];
                MMA16816(acc[tn], ah[s], bhp);   // hi*hi
                MMA16816(acc[tn], ah[s], blp);   // hi*lo
                MMA16816(acc[tn], al[s], bhp);   // lo*hi
            }
    }

    // epilogue
    const int er = lane >> 2;
    const int ec = (lane & 3) * 2;
    if constexpr (RAW) {
        float* Cp = C + (size_t)kz * 1024 * OUT;
#pragma unroll
        for (int tn = 0; tn < TNC; tn++) {
            const int row = bm + wm + er;
            const int col = bn + wn + tn * 8 + ec;
            *reinterpret_cast<float2*>(Cp + (size_t)row * OUT + col) =
                make_float2(acc[tn][0], acc[tn][1]);
            *reinterpret_cast<float2*>(Cp + (size_t)(row + 8) * OUT + col) =
                make_float2(acc[tn][2], acc[tn][3]);
        }
    } else {
#pragma unroll
        for (int tn = 0; tn < TNC; tn++) {
            const int row = bm + wm + er;
            const int col = bn + wn + tn * 8 + ec;
            float2 o0, o1;
            o0.x = logf(acc[tn][0]) + bias[col];
            o0.y = logf(acc[tn][1]) + bias[col + 1];
            o1.x = logf(acc[tn][2]) + bias[col];
            o1.y = logf(acc[tn][3]) + bias[col + 1];
            *reinterpret_cast<float2*>(C + (size_t)row * OUT + col) = o0;
            *reinterpret_cast<float2*>(C + (size_t)(row + 8) * OUT + col) = o1;
        }
    }
}

// ---------------------------------------------------------------------------
// Fused: sum 4 split-K partials -> log + linear bias -> trop_layernorm
// (median/IQR hybrid bitonic) -> relu -> exp -> bf16 hi/lo split.
// ---------------------------------------------------------------------------
__global__ __launch_bounds__(256) void ln_fuse_kernel(
    const float* __restrict__ P, const float* __restrict__ lb,
    const float* __restrict__ w, const float* __restrict__ b,
    __nv_bfloat16* __restrict__ Oh, __nv_bfloat16* __restrict__ Ol) {
    __shared__ float s[512];
    const int row = blockIdx.x;
    const int t = threadIdx.x;
    const size_t PS = (size_t)1024 * 512;
    const float* P0 = P + (size_t)row * 512;

    float s0 = P0[t] + P0[PS + t] + P0[2 * PS + t] + P0[3 * PS + t];
    float s1 = P0[t + 256] + P0[PS + t + 256] + P0[2 * PS + t + 256]
             + P0[3 * PS + t + 256];
    const float h0 = logf(s0) + lb[t];
    const float h1 = logf(s1) + lb[t + 256];
    float v0 = h0, v1 = h1;

#pragma unroll
    for (int k = 2; k <= 512; k <<= 1) {
        if (k == 512) {
            float m = fminf(v0, v1), M = fmaxf(v0, v1);
            v0 = m; v1 = M;
        }
#pragma unroll
        for (int j = (k >> 1) > 128 ? 128 : (k >> 1); j >= 32; j >>= 1) {
            __syncthreads();
            s[t] = v0; s[t + 256] = v1;
            __syncthreads();
            float p0 = s[t ^ j];
            float p1 = s[(t ^ j) + 256];
            bool asc0 = ((t & k) == 0);
            bool asc1 = (((t + 256) & k) == 0);
            bool low = ((t & j) == 0);
            v0 = (low == asc0) ? fminf(v0, p0) : fmaxf(v0, p0);
            v1 = (low == asc1) ? fminf(v1, p1) : fmaxf(v1, p1);
        }
#pragma unroll
        for (int j = (k >> 1) > 16 ? 16 : (k >> 1); j >= 1; j >>= 1) {
            bool asc0 = ((t & k) == 0);
            bool asc1 = (((t + 256) & k) == 0);
            bool low = ((t & j) == 0);
            float p0 = __shfl_xor_sync(0xffffffffu, v0, j);
            float p1 = __shfl_xor_sync(0xffffffffu, v1, j);
            v0 = (low == asc0) ? fminf(v0, p0) : fmaxf(v0, p0);
            v1 = (low == asc1) ? fminf(v1, p1) : fmaxf(v1, p1);
        }
    }

    __syncthreads();
    if (t == 127) { s[0] = v0; s[3] = v1; }
    if (t == 128) { s[1] = v0; s[4] = v1; }
    if (t == 255) { s[2] = v0; }
    __syncthreads();
    const float q25 = s[0] + 0.75f * (s[1] - s[0]);
    const float med = s[2];
    const float q75 = s[3] + 0.25f * (s[4] - s[3]);
    const float inv = 1.0f / fmaxf(q75 - q25, 1e-6f);

#pragma unroll
    for (int half = 0; half < 2; half++) {
        const int idx = t + half * 256;
        const float h = half ? h1 : h0;
        float o = fmaxf((h - med) * inv * w[idx] + b[idx], 0.0f);
        float e = expf(o);
        __nv_bfloat16 hi = __float2bfloat16(e);
        __nv_bfloat16 lo = __float2bfloat16(e - __bfloat162float(hi));
        Oh[row * 512 + idx] = hi;
        Ol[row * 512 + idx] = lo;
    }
}

// ---------------------------------------------------------------------------
extern "C" void kernel_launch(void* const* d_in, const int* in_sizes, int n_in,
                              void* d_out, int out_size) {
    const float* x    = (const float*)d_in[0];
    const float* w1   = (const float*)d_in[1];
    const float* b1   = (const float*)d_in[2];
    const float* ln1w = (const float*)d_in[3];
    const float* ln1b = (const float*)d_in[4];
    const float* w2   = (const float*)d_in[5];
    const float* b2   = (const float*)d_in[6];
    const float* ln2w = (const float*)d_in[7];
    const float* ln2b = (const float*)d_in[8];
    const float* w3   = (const float*)d_in[9];
    const float* b3   = (const float*)d_in[10];

    float* P;
    __nv_bfloat16 *Ah, *Al, *W1h, *W1l, *W2h, *W2l, *W3h, *W3l;
    cudaGetSymbolAddress((void**)&P, g_P);
    cudaGetSymbolAddress((void**)&Ah, g_Ah);
    cudaGetSymbolAddress((void**)&Al, g_Al);
    cudaGetSymbolAddress((void**)&W1h, g_W1h);
    cudaGetSymbolAddress((void**)&W1l, g_W1l);
    cudaGetSymbolAddress((void**)&W2h, g_W2h);
    cudaGetSymbolAddress((void**)&W2l, g_W2l);
    cudaGetSymbolAddress((void**)&W3h, g_W3h);
    cudaGetSymbolAddress((void**)&W3l, g_W3l);

    exp_split_kernel<<<1152, 256>>>(x, Ah, Al, w1, W1h, W1l, w2, W2h, W2l,
                                    w3, W3h, W3l);

    dim3 g12(512 / 64, 1024 / 64, 4);   // 8 x 16 x 4 = 512 CTAs (3.4/SM)
    dim3 g3(256 / 64, 1024 / 32, 1);    // 4 x 32 = 128 CTAs

    gemm_mma<64, 32, 4, true><<<g12, 256>>>(Ah, Al, W1h, W1l, nullptr, P, 512);
    ln_fuse_kernel<<<1024, 256>>>(P, b1, ln1w, ln1b, Ah, Al);
    gemm_mma<64, 32, 4, true><<<g12, 256>>>(Ah, Al, W2h, W2l, nullptr, P, 512);
    ln_fuse_kernel<<<1024, 256>>>(P, b2, ln2w, ln2b, Ah, Al);
    gemm_mma<32, 16, 16, false><<<g3, 256>>>(Ah, Al, W3h, W3l, b3,
                                             (float*)d_out, 256);
}

// round 17
// speedup vs baseline: 1.0915x; 1.0915x over previous
#include <cuda_runtime.h>
#include <cuda_bf16.h>
#include <math.h>
#include <cstdint>

// ---------------------------------------------------------------------------
// TropicalMLP: trop_linear(x;W,b) = log(exp(x) @ exp(W)^T) + b  (temp=1).
// exp values split fp32 = hi(bf16) + lo(bf16); GEMM = hh + hl + lh via
// mma.sync.m16n8k16 bf16.  R15: 128x64 CTA tile with 32x32 warp tiles
// (MMA:LDSM 3:1, half the per-output crossbar traffic), split-K x4,
// 2 CTAs/SM.  MMA passes ordered hh/hl/lh across all accumulators to break
// accumulator dependency chains.
// ---------------------------------------------------------------------------

#define KDIM 512
#define BKC  32          // K per chunk
#define LDSP 40          // padded row stride in bf16 (80 B)

__device__ float          g_P[4 * 1024 * 512];   // split-K partials
__device__ __nv_bfloat16  g_Ah[1024 * 512];
__device__ __nv_bfloat16  g_Al[1024 * 512];
__device__ __nv_bfloat16  g_W1h[512 * 512];
__device__ __nv_bfloat16  g_W1l[512 * 512];
__device__ __nv_bfloat16  g_W2h[512 * 512];
__device__ __nv_bfloat16  g_W2l[512 * 512];
__device__ __nv_bfloat16  g_W3h[256 * 512];
__device__ __nv_bfloat16  g_W3l[256 * 512];

__device__ __forceinline__ uint32_t smem_to_u32(const void* p) {
    uint32_t a;
    asm("{ .reg .u64 t; cvta.to.shared.u64 t, %1; cvt.u32.u64 %0, t; }"
        : "=r"(a) : "l"(p));
    return a;
}

#define LDSM4(r0, r1, r2, r3, addr)                                        \
    asm volatile("ldmatrix.sync.aligned.m8n8.x4.shared.b16 {%0,%1,%2,%3}, [%4];" \
                 : "=r"(r0), "=r"(r1), "=r"(r2), "=r"(r3) : "r"(addr))

#define MMA16816(d, a, b)                                                  \
    asm volatile("mma.sync.aligned.m16n8k16.row.col.f32.bf16.bf16.f32 "    \
                 "{%0,%1,%2,%3}, {%4,%5,%6,%7}, {%8,%9}, {%0,%1,%2,%3};"   \
                 : "+f"((d)[0]), "+f"((d)[1]), "+f"((d)[2]), "+f"((d)[3])  \
                 : "r"((a)[0]), "r"((a)[1]), "r"((a)[2]), "r"((a)[3]),     \
                   "r"((b)[0]), "r"((b)[1]))

#define CP_ASYNC16(dst, src)                                               \
    asm volatile("cp.async.ca.shared.global [%0], [%1], 16;"               \
                 :: "r"(dst), "l"(src))
#define CP_COMMIT() asm volatile("cp.async.commit_group;" ::: "memory")
#define CP_WAIT1()  asm volatile("cp.async.wait_group 1;" ::: "memory")

// ---------------------------------------------------------------------------
// exp + hi/lo split of x, w1, w2, w3 (float4 granular)
// ---------------------------------------------------------------------------
__global__ __launch_bounds__(256) void exp_split_kernel(
    const float* __restrict__ x,  __nv_bfloat16* __restrict__ xh, __nv_bfloat16* __restrict__ xl,
    const float* __restrict__ w1, __nv_bfloat16* __restrict__ w1h, __nv_bfloat16* __restrict__ w1l,
    const float* __restrict__ w2, __nv_bfloat16* __restrict__ w2h, __nv_bfloat16* __restrict__ w2l,
    const float* __restrict__ w3, __nv_bfloat16* __restrict__ w3h, __nv_bfloat16* __restrict__ w3l) {
    int i = blockIdx.x * 256 + threadIdx.x;  // float4 index
    const float* s; __nv_bfloat16 *dh, *dl; int off;
    if (i < 131072)      { s = x;  dh = xh;  dl = xl;  off = i; }
    else if (i < 196608) { s = w1; dh = w1h; dl = w1l; off = i - 131072; }
    else if (i < 262144) { s = w2; dh = w2h; dl = w2l; off = i - 196608; }
    else                 { s = w3; dh = w3h; dl = w3l; off = i - 262144; }
    float4 v = reinterpret_cast<const float4*>(s)[off];
    float e[4] = {expf(v.x), expf(v.y), expf(v.z), expf(v.w)};
#pragma unroll
    for (int j = 0; j < 4; j++) {
        __nv_bfloat16 hi = __float2bfloat16(e[j]);
        __nv_bfloat16 lo = __float2bfloat16(e[j] - __bfloat162float(hi));
        dh[off * 4 + j] = hi;
        dl[off * 4 + j] = lo;
    }
}

// ---------------------------------------------------------------------------
// HMMA GEMM:  acc[m,n] = (Ah+Al)[m,kz-chunk].(Bh+Bl)[n,kz-chunk]
// BM x 64 CTA tile, 8 warps, warp tile WM x WN, KCH chunks of 32 K,
// 3-stage cp.async pipeline.  RAW=true: raw partials at C + kz*1024*OUT.
// ---------------------------------------------------------------------------
template <int BM, int WM, int WN, int KCH, bool RAW>
__global__ __launch_bounds__(256, 2) void gemm_mma(
    const __nv_bfloat16* __restrict__ Ah, const __nv_bfloat16* __restrict__ Al,
    const __nv_bfloat16* __restrict__ Bh, const __nv_bfloat16* __restrict__ Bl,
    const float* __restrict__ bias, float* __restrict__ C, int OUT) {
    constexpr int BN = 64, S = 3;
    constexpr int TMC = WM / 16;     // A 16-row m-tiles per warp
    constexpr int PN  = WN / 16;     // B 16-row groups per warp
    constexpr int TNC = WN / 8;      // mma n-tiles per warp
    constexpr int NWM = BM / WM;     // warps along M
    constexpr int NWN = BN / WN;     // warps along N
    static_assert(NWM * NWN == 8, "8 warps");

    __shared__ __align__(16) __nv_bfloat16 sA[S][2][BM][LDSP];
    __shared__ __align__(16) __nv_bfloat16 sB[S][2][BN][LDSP];

    const int tid  = threadIdx.x;
    const int lane = tid & 31;
    const int warp = tid >> 5;
    const int wm = (warp / NWN) * WM;
    const int wn = (warp % NWN) * WN;
    const int bm = blockIdx.y * BM;
    const int bn = blockIdx.x * BN;
    const int kz = blockIdx.z;
    const int kbase = kz * KCH * BKC;

    const uint32_t sAb = smem_to_u32(sA);
    const uint32_t sBb = smem_to_u32(sB);
    constexpr uint32_t A_ARR = BM * LDSP * 2, A_STG = 2 * A_ARR;
    constexpr uint32_t B_ARR = BN * LDSP * 2, B_STG = 2 * B_ARR;

    // cp.async mapping: thread -> (row, 16B seg); rows strided by 64
    const int grow = tid >> 2, gseg = tid & 3;
    const __nv_bfloat16* gpA[2] = {Ah + (size_t)bm * KDIM, Al + (size_t)bm * KDIM};
    const __nv_bfloat16* gpB[2] = {Bh + (size_t)bn * KDIM, Bl + (size_t)bn * KDIM};

    // ldmatrix lane addressing
    const int rowA = lane & 15, chA = lane >> 4;
    const int qB = lane >> 3;
    const int rowB = ((qB >> 1) << 3) + (lane & 7), colB = (qB & 1) * 8;
    uint32_t aBase[2][TMC], bBase[2][PN];
#pragma unroll
    for (int a = 0; a < 2; a++)
#pragma unroll
        for (int tm = 0; tm < TMC; tm++)
            aBase[a][tm] = sAb + a * A_ARR +
                ((uint32_t)(wm + tm * 16 + rowA) * LDSP + chA * 8) * 2;
#pragma unroll
    for (int a = 0; a < 2; a++)
#pragma unroll
        for (int p = 0; p < PN; p++)
            bBase[a][p] = sBb + a * B_ARR +
                ((uint32_t)(wn + p * 16 + rowB) * LDSP + colB) * 2;

    float acc[TMC][TNC][4] = {};

    auto copy_chunk = [&](int c, int buf) {
        const int k0 = kbase + c * BKC;
#pragma unroll
        for (int r0 = 0; r0 < BM; r0 += 64) {
            const int r = r0 + grow;
            if (r < BM) {
#pragma unroll
                for (int a = 0; a < 2; a++) {
                    uint32_t dst = sAb + buf * A_STG + a * A_ARR +
                                   ((uint32_t)r * LDSP + gseg * 8) * 2;
                    CP_ASYNC16(dst, gpA[a] + (size_t)r * KDIM + k0 + gseg * 8);
                }
            }
        }
#pragma unroll
        for (int a = 0; a < 2; a++) {
            uint32_t dst = sBb + buf * B_STG + a * B_ARR +
                           ((uint32_t)grow * LDSP + gseg * 8) * 2;
            CP_ASYNC16(dst, gpB[a] + (size_t)grow * KDIM + k0 + gseg * 8);
        }
        CP_COMMIT();
    };

    copy_chunk(0, 0);
    copy_chunk(1, 1);

#pragma unroll 1
    for (int c = 0; c < KCH; c++) {
        CP_WAIT1();              // chunk c landed
        __syncthreads();
        if (c + 2 < KCH) copy_chunk(c + 2, (c + 2) % S);
        else             CP_COMMIT();   // keep group numbering uniform

        const uint32_t ao = (c % S) * A_STG, bo = (c % S) * B_STG;
#pragma unroll
        for (int s = 0; s < 2; s++) {
            const uint32_t so = s * 32;  // 16 bf16 = 32 B
            uint32_t ah[TMC][4], al[TMC][4], bh[PN][4], bl[PN][4];
#pragma unroll
            for (int tm = 0; tm < TMC; tm++) {
                LDSM4(ah[tm][0], ah[tm][1], ah[tm][2], ah[tm][3],
                      aBase[0][tm] + ao + so);
                LDSM4(al[tm][0], al[tm][1], al[tm][2], al[tm][3],
                      aBase[1][tm] + ao + so);
            }
#pragma unroll
            for (int p = 0; p < PN; p++) {
                LDSM4(bh[p][0], bh[p][1], bh[p][2], bh[p][3],
                      bBase[0][p] + bo + so);
                LDSM4(bl[p][0], bl[p][1], bl[p][2], bl[p][3],
                      bBase[1][p] + bo + so);
            }
            // three passes, each sweeping all accumulators -> no acc chains
#pragma unroll
            for (int tm = 0; tm < TMC; tm++)
#pragma unroll
                for (int tn = 0; tn < TNC; tn++)
                    MMA16816(acc[tm][tn], ah[tm], (&bh[tn >> 1][(tn & 1) * 2]));
#pragma unroll
            for (int tm = 0; tm < TMC; tm++)
#pragma unroll
                for (int tn = 0; tn < TNC; tn++)
                    MMA16816(acc[tm][tn], ah[tm], (&bl[tn >> 1][(tn & 1) * 2]));
#pragma unroll
            for (int tm = 0; tm < TMC; tm++)
#pragma unroll
                for (int tn = 0; tn < TNC; tn++)
                    MMA16816(acc[tm][tn], al[tm], (&bh[tn >> 1][(tn & 1) * 2]));
        }
    }

    // epilogue
    const int er = lane >> 2;
    const int ec = (lane & 3) * 2;
    if constexpr (RAW) {
        float* Cp = C + (size_t)kz * 1024 * OUT;
#pragma unroll
        for (int tm = 0; tm < TMC; tm++)
#pragma unroll
            for (int tn = 0; tn < TNC; tn++) {
                const int row = bm + wm + tm * 16 + er;
                const int col = bn + wn + tn * 8 + ec;
                *reinterpret_cast<float2*>(Cp + (size_t)row * OUT + col) =
                    make_float2(acc[tm][tn][0], acc[tm][tn][1]);
                *reinterpret_cast<float2*>(Cp + (size_t)(row + 8) * OUT + col) =
                    make_float2(acc[tm][tn][2], acc[tm][tn][3]);
            }
    } else {
#pragma unroll
        for (int tm = 0; tm < TMC; tm++)
#pragma unroll
            for (int tn = 0; tn < TNC; tn++) {
                const int row = bm + wm + tm * 16 + er;
                const int col = bn + wn + tn * 8 + ec;
                float2 o0, o1;
                o0.x = logf(acc[tm][tn][0]) + bias[col];
                o0.y = logf(acc[tm][tn][1]) + bias[col + 1];
                o1.x = logf(acc[tm][tn][2]) + bias[col];
                o1.y = logf(acc[tm][tn][3]) + bias[col + 1];
                *reinterpret_cast<float2*>(C + (size_t)row * OUT + col) = o0;
                *reinterpret_cast<float2*>(C + (size_t)(row + 8) * OUT + col) = o1;
            }
    }
}

// ---------------------------------------------------------------------------
// Fused: sum 4 split-K partials -> log + linear bias -> trop_layernorm
// (median/IQR hybrid bitonic) -> relu -> exp -> bf16 hi/lo split.
// ---------------------------------------------------------------------------
__global__ __launch_bounds__(256) void ln_fuse_kernel(
    const float* __restrict__ P, const float* __restrict__ lb,
    const float* __restrict__ w, const float* __restrict__ b,
    __nv_bfloat16* __restrict__ Oh, __nv_bfloat16* __restrict__ Ol) {
    __shared__ float s[512];
    const int row = blockIdx.x;
    const int t = threadIdx.x;
    const size_t PS = (size_t)1024 * 512;
    const float* P0 = P + (size_t)row * 512;

    float s0 = P0[t] + P0[PS + t] + P0[2 * PS + t] + P0[3 * PS + t];
    float s1 = P0[t + 256] + P0[PS + t + 256] + P0[2 * PS + t + 256]
             + P0[3 * PS + t + 256];
    const float h0 = logf(s0) + lb[t];
    const float h1 = logf(s1) + lb[t + 256];
    float v0 = h0, v1 = h1;

#pragma unroll
    for (int k = 2; k <= 512; k <<= 1) {
        if (k == 512) {
            float m = fminf(v0, v1), M = fmaxf(v0, v1);
            v0 = m; v1 = M;
        }
#pragma unroll
        for (int j = (k >> 1) > 128 ? 128 : (k >> 1); j >= 32; j >>= 1) {
            __syncthreads();
            s[t] = v0; s[t + 256] = v1;
            __syncthreads();
            float p0 = s[t ^ j];
            float p1 = s[(t ^ j) + 256];
            bool asc0 = ((t & k) == 0);
            bool asc1 = (((t + 256) & k) == 0);
            bool low = ((t & j) == 0);
            v0 = (low == asc0) ? fminf(v0, p0) : fmaxf(v0, p0);
            v1 = (low == asc1) ? fminf(v1, p1) : fmaxf(v1, p1);
        }
#pragma unroll
        for (int j = (k >> 1) > 16 ? 16 : (k >> 1); j >= 1; j >>= 1) {
            bool asc0 = ((t & k) == 0);
            bool asc1 = (((t + 256) & k) == 0);
            bool low = ((t & j) == 0);
            float p0 = __shfl_xor_sync(0xffffffffu, v0, j);
            float p1 = __shfl_xor_sync(0xffffffffu, v1, j);
            v0 = (low == asc0) ? fminf(v0, p0) : fmaxf(v0, p0);
            v1 = (low == asc1) ? fminf(v1, p1) : fmaxf(v1, p1);
        }
    }

    __syncthreads();
    if (t == 127) { s[0] = v0; s[3] = v1; }
    if (t == 128) { s[1] = v0; s[4] = v1; }
    if (t == 255) { s[2] = v0; }
    __syncthreads();
    const float q25 = s[0] + 0.75f * (s[1] - s[0]);
    const float med = s[2];
    const float q75 = s[3] + 0.25f * (s[4] - s[3]);
    const float inv = 1.0f / fmaxf(q75 - q25, 1e-6f);

#pragma unroll
    for (int half = 0; half < 2; half++) {
        const int idx = t + half * 256;
        const float h = half ? h1 : h0;
        float o = fmaxf((h - med) * inv * w[idx] + b[idx], 0.0f);
        float e = expf(o);
        __nv_bfloat16 hi = __float2bfloat16(e);
        __nv_bfloat16 lo = __float2bfloat16(e - __bfloat162float(hi));
        Oh[row * 512 + idx] = hi;
        Ol[row * 512 + idx] = lo;
    }
}

// ---------------------------------------------------------------------------
extern "C" void kernel_launch(void* const* d_in, const int* in_sizes, int n_in,
                              void* d_out, int out_size) {
    const float* x    = (const float*)d_in[0];
    const float* w1   = (const float*)d_in[1];
    const float* b1   = (const float*)d_in[2];
    const float* ln1w = (const float*)d_in[3];
    const float* ln1b = (const float*)d_in[4];
    const float* w2   = (const float*)d_in[5];
    const float* b2   = (const float*)d_in[6];
    const float* ln2w = (const float*)d_in[7];
    const float* ln2b = (const float*)d_in[8];
    const float* w3   = (const float*)d_in[9];
    const float* b3   = (const float*)d_in[10];

    float* P;
    __nv_bfloat16 *Ah, *Al, *W1h, *W1l, *W2h, *W2l, *W3h, *W3l;
    cudaGetSymbolAddress((void**)&P, g_P);
    cudaGetSymbolAddress((void**)&Ah, g_Ah);
    cudaGetSymbolAddress((void**)&Al, g_Al);
    cudaGetSymbolAddress((void**)&W1h, g_W1h);
    cudaGetSymbolAddress((void**)&W1l, g_W1l);
    cudaGetSymbolAddress((void**)&W2h, g_W2h);
    cudaGetSymbolAddress((void**)&W2l, g_W2l);
    cudaGetSymbolAddress((void**)&W3h, g_W3h);
    cudaGetSymbolAddress((void**)&W3l, g_W3l);

    exp_split_kernel<<<1152, 256>>>(x, Ah, Al, w1, W1h, W1l, w2, W2h, W2l,
                                    w3, W3h, W3l);

    dim3 g12(512 / 64, 1024 / 128, 4);   // 8 x 8 x 4 = 256 CTAs
    dim3 g3(256 / 64, 1024 / 32, 1);     // 4 x 32 = 128 CTAs

    gemm_mma<128, 32, 32, 4, true><<<g12, 256>>>(Ah, Al, W1h, W1l, nullptr,
                                                 P, 512);
    ln_fuse_kernel<<<1024, 256>>>(P, b1, ln1w, ln1b, Ah, Al);
    gemm_mma<128, 32, 32, 4, true><<<g12, 256>>>(Ah, Al, W2h, W2l, nullptr,
                                                 P, 512);
    ln_fuse_kernel<<<1024, 256>>>(P, b2, ln2w, ln2b, Ah, Al);
    gemm_mma<32, 16, 16, 16, false><<<g3, 256>>>(Ah, Al, W3h, W3l, b3,
                                                 (float*)d_out, 256);
}